// round 9
// baseline (speedup 1.0000x reference)
#include <cuda_runtime.h>
#include <cuda_bf16.h>
#include <cstdint>

#define IN_F   4096
#define OUT_F  4096
#define NTOK   16384
#define BW     8
#define KW     17          // 2*BW+1
#define NO     4           // outputs per thread
#define WARPS  8           // warps per block (256 threads)
#define GY     256         // token stride / grid.y  -> 64 tokens per block
#define WIN4   36          // float4 chunks per warp window (144 floats)
#define SBUF4  40          // chunks per buffer
#define NBUF   8           // two halves of 4
#define UNR    4           // tokens per wait
#define PDIST  4           // prefetch distance (groups in flight)
#define BROWS  (WARPS * 32 * NO)           // 1024 band rows per block
#define WST_F  (BROWS * KW)                // 17408 staged weight floats
#define PIPE_B (WARPS * NBUF * SBUF4 * 16) // 40960 B
#define WST_B  (WST_F * 4)                 // 69632 B
#define SMEM_B (WST_B > PIPE_B ? WST_B : PIPE_B)   // union: 69632 B

__device__ __forceinline__ void cp16(uint32_t dst_smem, const float* src) {
    asm volatile("cp.async.cg.shared.global [%0], [%1], 16;\n"
                 :: "r"(dst_smem), "l"(src) : "memory");
}
__device__ __forceinline__ void cp4(uint32_t dst_smem, const float* src) {
    asm volatile("cp.async.ca.shared.global [%0], [%1], 4;\n"
                 :: "r"(dst_smem), "l"(src) : "memory");
}
__device__ __forceinline__ void cp_commit() {
    asm volatile("cp.async.commit_group;\n" ::: "memory");
}

// warp covers 32*NO = 128 consecutive outputs; block covers 1024; grid.x = 4.
__global__ __launch_bounds__(256, 2) void band_linear_kernel(
    const float* __restrict__ x,
    const float* __restrict__ w,
    const float* __restrict__ bias,
    float* __restrict__ out)
{
    extern __shared__ char dsm[];
    float4* smp = reinterpret_cast<float4*>(dsm);         // x pipeline (after weights consumed)
    float*  smw = reinterpret_cast<float*>(dsm);          // weight stage (union)

    const int warp = threadIdx.x >> 5;
    const int lane = threadIdx.x & 31;
    const int wbase  = (blockIdx.x * WARPS + warp) * (32 * NO);
    const int o_base = wbase + lane * NO;
    const int win0   = wbase - BW;               // multiple of 4

    // ---- async coalesced weight staging: 1024 rows x 17 taps, one group ----
    {
        const int row0 = blockIdx.x * BROWS;
        const uint32_t smw_a = (uint32_t)__cvta_generic_to_shared(smw);
#pragma unroll
        for (int i = 0; i < WST_F / 256; ++i) {              // 68 cp.async each
            const int e = threadIdx.x + i * 256;
            const int r = e / KW;
            const int k = e - r * KW;
            const int o = row0 + r;
            int col = o - BW + k;
            col = col < 0 ? 0 : (col >= IN_F ? IN_F - 1 : col);  // clamp; zeroed later
            cp4(smw_a + (uint32_t)(e * 4), w + (long)o * IN_F + col);
        }
        cp_commit();
    }
    asm volatile("cp.async.wait_group 0;\n" ::: "memory");
    __syncthreads();

    // ---- copy weights smem -> registers, then smem is recycled for x ----
    float wr[NO][KW];
    float br[NO];
    {
        const int rloc = warp * 128 + lane * NO;
#pragma unroll
        for (int oo = 0; oo < NO; ++oo) {
            const int o = o_base + oo;
            br[oo] = bias[o];
#pragma unroll
            for (int k = 0; k < KW; ++k) {
                const int col = o - BW + k;
                const float v = smw[(rloc + oo) * KW + k];
                wr[oo][k] = (col >= 0 && col < IN_F) ? v : 0.0f;
            }
        }
    }
    __syncthreads();   // all reads of smw done before pipeline overwrites it

    // ---- x staging chunk assignment (coalesced, 36 chunks over 32 lanes) ----
    const int  c0    = lane;
    const bool extra = (lane < WIN4 - 32);   // lanes 0..3 take chunks 32..35
    const int  c1    = 32 + lane;

    int s0 = win0 + 4 * c0;
    s0 = s0 < 0 ? 0 : (s0 > IN_F - 4 ? IN_F - 4 : s0);
    int s1 = win0 + 4 * c1;
    s1 = s1 < 0 ? 0 : (s1 > IN_F - 4 ? IN_F - 4 : s1);
    // clamped chunks pair only with zero weights -> harmless.

    const uint32_t wsm  = (uint32_t)__cvta_generic_to_shared(smp + (size_t)warp * NBUF * SBUF4);
    const uint32_t off0 = (uint32_t)(c0 * 16);
    const uint32_t off1 = (uint32_t)(c1 * 16);

    const int n0 = blockIdx.y;

    // ---- prologue: stage tokens n0 .. n0+3*GY into buffers 0..3 ----
#pragma unroll
    for (int p = 0; p < UNR; ++p) {
        const int tn = n0 + p * GY;        // always < NTOK
        const float* xrow = x + (long)tn * IN_F;
        const uint32_t b = wsm + (uint32_t)(p * SBUF4 * 16);
        cp16(b + off0, xrow + s0);
        if (extra) cp16(b + off1, xrow + s1);
        cp_commit();
    }

    int half = 0;   // which half of the 8 buffers holds the current 4 tokens
    for (int n = n0; n < NTOK; n += UNR * GY) {
        const uint32_t pb = wsm + (uint32_t)((half ^ 1) * UNR * SBUF4 * 16);

        // ---- stage tokens n+4*GY .. n+7*GY into the other half (4 groups) ----
#pragma unroll
        for (int p = 0; p < UNR; ++p) {
            const int pn = n + (UNR + p) * GY;
            if (pn < NTOK) {
                const float* xrow = x + (long)pn * IN_F;
                const uint32_t b = pb + (uint32_t)(p * SBUF4 * 16);
                cp16(b + off0, xrow + s0);
                if (extra) cp16(b + off1, xrow + s1);
            }
            cp_commit();
        }

        // ---- wait: <= 4 groups pending => current half's 4 buffers complete ----
        asm volatile("cp.async.wait_group %0;\n" :: "n"(PDIST) : "memory");
        __syncwarp();

        const float* cb = reinterpret_cast<const float*>(smp + (size_t)warp * NBUF * SBUF4)
                        + (size_t)half * UNR * SBUF4 * 4;

        // ---- compute 4 tokens sequentially from static buffer offsets ----
#pragma unroll
        for (int t = 0; t < UNR; ++t) {
            const float* swp = cb + (size_t)t * SBUF4 * 4;
            float xr[NO + 2 * BW];  // 20
#pragma unroll
            for (int c = 0; c < 5; ++c) {
                const float4 v = *reinterpret_cast<const float4*>(swp + lane * NO + 4 * c);
                xr[4 * c + 0] = v.x;
                xr[4 * c + 1] = v.y;
                xr[4 * c + 2] = v.z;
                xr[4 * c + 3] = v.w;
            }
            float acc[NO];
#pragma unroll
            for (int oo = 0; oo < NO; ++oo) {
                float a = br[oo];
#pragma unroll
                for (int k = 0; k < KW; ++k)
                    a = fmaf(wr[oo][k], xr[oo + k], a);
                acc[oo] = a;
            }
            float4 o4;
            o4.x = acc[0]; o4.y = acc[1]; o4.z = acc[2]; o4.w = acc[3];
            *reinterpret_cast<float4*>(out + (long)(n + t * GY) * OUT_F + o_base) = o4;
        }

        half ^= 1;
    }
}

extern "C" void kernel_launch(void* const* d_in, const int* in_sizes, int n_in,
                              void* d_out, int out_size)
{
    const float* x    = (const float*)d_in[0];   // [NTOK, IN_F]
    const float* w    = (const float*)d_in[1];   // [OUT_F, IN_F]
    const float* bias = (const float*)d_in[2];   // [OUT_F]
    float* out = (float*)d_out;

    cudaFuncSetAttribute(band_linear_kernel,
                         cudaFuncAttributeMaxDynamicSharedMemorySize, SMEM_B);

    dim3 grid(OUT_F / (WARPS * 32 * NO), GY);    // (4, 256)
    dim3 block(WARPS * 32);                      // 256
    band_linear_kernel<<<grid, block, SMEM_B>>>(x, w, bias, out);
}